// round 4
// baseline (speedup 1.0000x reference)
#include <cuda_runtime.h>

#define T_LEN 1024

struct Params {
    float INSC, COEFF, SMSC, SUB, CRAK, RecK, invSMSC, cexp;
};

// One scan step. Returns Q for this timestep's *entering* state (which, due to
// the reference's roll(shift=1), is exactly Q[t] for t >= 1). Updates SMS/GW.
__device__ __forceinline__ float stepQ(float Prec, float PET,
                                       float& SMS, float& GW,
                                       const Params& P)
{
    // soil_moisture_store: clip(SMS, 0, SMSC); SMS >= 0 is an invariant.
    float SMSc = fminf(SMS, P.SMSC);
    // interception: INT = min(INSC, PET, Prec)  (all operands >= 0)
    float INT  = fminf(fminf(P.INSC, PET), Prec);
    float INR  = Prec - INT;                       // >= 0
    // cap = COEFF * exp(-SQ*SMS/SMSC); heaviside blend == min at 1e-3 tol
    float cap  = P.COEFF * __expf(SMSc * P.cexp);
    float RMO  = fminf(INR, cap);
    float frac = SMSc * P.invSMSC;
    float SRUN = (P.SUB * frac) * RMO;
    float RS   = RMO - SRUN;
    float REC  = (P.CRAK * frac) * RS;
    float SMF  = RS - REC;                         // >= 0
    float POT  = PET - INT;                        // >= 0 (INT <= PET)
    float ETS  = fminf(POT, 10.0f * frac);
    float s    = SMSc + (SMF - ETS);               // next_SMS (clip ±1e5 never binds)
    float RECn = REC + fmaxf(s - P.SMSC, 0.0f);    // recharge_calculation
    float BAS  = P.RecK * GW;                      // GW >= 0 invariant
    float Q    = (SRUN + (INR - RMO)) + BAS;       // DR + GD, all terms >= 0
    SMS = s;
    GW  = GW + (RECn - BAS);                       // clip ±1e5 never binds
    return Q;
}

__global__ void __launch_bounds__(128)
hirnn_kernel(const float* __restrict__ in, float* __restrict__ out,
             const float* __restrict__ pINSC, const float* __restrict__ pCOEFF,
             const float* __restrict__ pSQ,   const float* __restrict__ pSMSC,
             const float* __restrict__ pSUB,  const float* __restrict__ pCRAK,
             const float* __restrict__ pRecK, int B)
{
    int b = blockIdx.x * blockDim.x + threadIdx.x;
    if (b >= B) return;

    Params P;
    P.INSC    = fminf(fmaxf(pINSC[0]  * 5.0f,   0.5f),  5.0f);
    P.COEFF   = fminf(fmaxf(pCOEFF[0] * 400.0f, 50.0f), 400.0f);
    float SQ  = fminf(fmaxf(pSQ[0]    * 6.0f,   0.0f),  6.0f);
    P.SMSC    = fminf(fmaxf(pSMSC[0]  * 500.0f, 50.0f), 500.0f);
    P.SUB     = fminf(fmaxf(pSUB[0],            0.0f),  1.0f);
    P.CRAK    = fminf(fmaxf(pCRAK[0],           0.0f),  1.0f);
    P.RecK    = fminf(fmaxf(pRecK[0]  * 0.3f,   0.003f), 0.3f);
    P.invSMSC = 1.0f / P.SMSC;
    P.cexp    = -SQ * P.invSMSC;

    const float4* inp = reinterpret_cast<const float4*>(in + (size_t)b * (2 * T_LEN));
    float4*       qo  = reinterpret_cast<float4*>(out + (size_t)b * T_LEN);

    float SMS = 0.0f, GW = 0.0f;

    #pragma unroll 4
    for (int t4 = 0; t4 < T_LEN / 4; ++t4) {
        float4 a = inp[2 * t4];       // timesteps 4t4, 4t4+1
        float4 c = inp[2 * t4 + 1];   // timesteps 4t4+2, 4t4+3
        float4 q;
        q.x = stepQ(a.x, a.y, SMS, GW, P);
        q.y = stepQ(a.z, a.w, SMS, GW, P);
        q.z = stepQ(c.x, c.y, SMS, GW, P);
        q.w = stepQ(c.z, c.w, SMS, GW, P);
        qo[t4] = q;
    }

    // Q[0]: roll wraps the FINAL state to t=0. Recompute one step with the
    // t=0 inputs and the post-scan state, overwrite the loop's t=0 value.
    float2 x0 = reinterpret_cast<const float2*>(in + (size_t)b * (2 * T_LEN))[0];
    float q0  = stepQ(x0.x, x0.y, SMS, GW, P);
    out[(size_t)b * T_LEN] = q0;
}

extern "C" void kernel_launch(void* const* d_in, const int* in_sizes, int n_in,
                              void* d_out, int out_size)
{
    const float* in = (const float*)d_in[0];
    int B = in_sizes[0] / (2 * T_LEN);
    int block = 128;
    int grid  = (B + block - 1) / block;
    hirnn_kernel<<<grid, block>>>(in, (float*)d_out,
                                  (const float*)d_in[1], (const float*)d_in[2],
                                  (const float*)d_in[3], (const float*)d_in[4],
                                  (const float*)d_in[5], (const float*)d_in[6],
                                  (const float*)d_in[7], B);
}

// round 6
// speedup vs baseline: 2.2719x; 2.2719x over previous
#include <cuda_runtime.h>

#define T_LEN 1024
#define CH 16                 // timesteps per prefetch chunk
#define NCHUNK (T_LEN / CH)   // 64

struct Pr {
    float INSC, COEFF, SMSC, SUB10, CRAK10, RecK, kGW, inv10, cexp2;
};

__device__ __forceinline__ float ex2f(float x) {
    float r; asm("ex2.approx.ftz.f32 %0, %1;" : "=f"(r) : "f"(x)); return r;
}

// One scan step on pre-clipped state SMSc in [0, SMSC], GW >= 0 (up to rounding).
// Returns Q[t] for the state ENTERING the step (matches reference's roll(1)).
__device__ __forceinline__ float stepQ(float Prec, float PET,
                                       float& SMSc, float& GW, const Pr& p)
{
    float arg  = SMSc * p.cexp2;                 // exp2 argument (log2e folded in)
    float tf   = SMSc * p.inv10;                 // 10 * SMSc / SMSC
    float INT  = fminf(fminf(p.INSC, PET), Prec);
    float INR  = Prec - INT;
    float POT  = PET - INT;
    float ETS  = fminf(POT, tf);
    float a1   = fmaf(-p.SUB10,  tf, 1.0f);      // 1 - SUB*frac
    float a2   = fmaf(-p.CRAK10, tf, 1.0f);      // 1 - CRAK*frac
    float g    = a1 * a2;
    float base = SMSc - ETS;
    float cap  = p.COEFF * ex2f(arg);            // COEFF * exp(-SQ*SMSc/SMSC)
    float RMO  = fminf(INR, cap);                // heaviside blend == min
    float s    = fmaf(RMO, g, base);             // next SMS (pre-clip); SMF = RMO*g
    float h    = RMO * a1;                       // RMO - SRUN
    float ns   = fminf(s, p.SMSC);               // next clipped store
    float RECn = h + (base - ns);                // REC + overflow (s terms cancel)
    float Q    = fmaf(p.RecK, GW, INR - h);      // (IRUN+SRUN) + BAS
    GW   = fmaf(GW, p.kGW, RECn);                // GW*(1-RecK) + RECn
    SMSc = ns;
    return Q;
}

__global__ void __launch_bounds__(32)
hirnn_kernel(const float* __restrict__ in, float* __restrict__ out,
             const float* __restrict__ pINSC, const float* __restrict__ pCOEFF,
             const float* __restrict__ pSQ,   const float* __restrict__ pSMSC,
             const float* __restrict__ pSUB,  const float* __restrict__ pCRAK,
             const float* __restrict__ pRecK, int B)
{
    int b = blockIdx.x * 32 + threadIdx.x;
    if (b >= B) return;

    Pr p;
    p.INSC      = fminf(fmaxf(pINSC[0]  * 5.0f,   0.5f),   5.0f);
    p.COEFF     = fminf(fmaxf(pCOEFF[0] * 400.0f, 50.0f),  400.0f);
    float SQ    = fminf(fmaxf(pSQ[0]    * 6.0f,   0.0f),   6.0f);
    p.SMSC      = fminf(fmaxf(pSMSC[0]  * 500.0f, 50.0f),  500.0f);
    float SUB   = fminf(fmaxf(pSUB[0],            0.0f),   1.0f);
    float CRAK  = fminf(fmaxf(pCRAK[0],           0.0f),   1.0f);
    p.RecK      = fminf(fmaxf(pRecK[0]  * 0.3f,   0.003f), 0.3f);
    p.kGW       = 1.0f - p.RecK;
    float invS  = 1.0f / p.SMSC;
    p.inv10     = 10.0f * invS;                  // tf = SMSc * inv10 = 10*frac
    p.SUB10     = SUB  * 0.1f;                   // SUB*frac  = SUB10 * tf
    p.CRAK10    = CRAK * 0.1f;                   // CRAK*frac = CRAK10 * tf
    p.cexp2     = -SQ * invS * 1.44269504088896f; // exp(x) = exp2(x*log2e)

    const float4* inp = reinterpret_cast<const float4*>(in + (size_t)b * (2 * T_LEN));
    float4*       qo  = reinterpret_cast<float4*>(out + (size_t)b * T_LEN);

    float SMS = 0.0f, GW = 0.0f;

    // Register double-buffer: prefetch next CH timesteps (CH/2 float4s) while
    // computing the current chunk, hiding DRAM latency under the serial chain.
    float4 buf[CH / 2];
    #pragma unroll
    for (int i = 0; i < CH / 2; ++i) buf[i] = inp[i];

    for (int c = 0; c < NCHUNK - 1; ++c) {
        float4 cur[CH / 2];
        #pragma unroll
        for (int i = 0; i < CH / 2; ++i) cur[i] = buf[i];
        #pragma unroll
        for (int i = 0; i < CH / 2; ++i) buf[i] = inp[(c + 1) * (CH / 2) + i];

        #pragma unroll
        for (int q4 = 0; q4 < CH / 4; ++q4) {
            float4 A = cur[2 * q4];
            float4 C = cur[2 * q4 + 1];
            float4 q;
            q.x = stepQ(A.x, A.y, SMS, GW, p);
            q.y = stepQ(A.z, A.w, SMS, GW, p);
            q.z = stepQ(C.x, C.y, SMS, GW, p);
            q.w = stepQ(C.z, C.w, SMS, GW, p);
            qo[c * (CH / 4) + q4] = q;
        }
    }
    // last chunk (no prefetch)
    {
        const int c = NCHUNK - 1;
        #pragma unroll
        for (int q4 = 0; q4 < CH / 4; ++q4) {
            float4 A = buf[2 * q4];
            float4 C = buf[2 * q4 + 1];
            float4 q;
            q.x = stepQ(A.x, A.y, SMS, GW, p);
            q.y = stepQ(A.z, A.w, SMS, GW, p);
            q.z = stepQ(C.x, C.y, SMS, GW, p);
            q.w = stepQ(C.z, C.w, SMS, GW, p);
            qo[c * (CH / 4) + q4] = q;
        }
    }

    // Q[0]: roll wraps the FINAL state to t=0 — one extra step with t=0 inputs.
    float2 x0 = reinterpret_cast<const float2*>(in + (size_t)b * (2 * T_LEN))[0];
    out[(size_t)b * T_LEN] = stepQ(x0.x, x0.y, SMS, GW, p);
}

extern "C" void kernel_launch(void* const* d_in, const int* in_sizes, int n_in,
                              void* d_out, int out_size)
{
    const float* in = (const float*)d_in[0];
    int B = in_sizes[0] / (2 * T_LEN);
    int block = 32;                      // 1 warp per block -> 1 warp per SM/SMSP
    int grid  = (B + block - 1) / block; // 128 blocks -> ~all SMs, no L1tex sharing
    hirnn_kernel<<<grid, block>>>(in, (float*)d_out,
                                  (const float*)d_in[1], (const float*)d_in[2],
                                  (const float*)d_in[3], (const float*)d_in[4],
                                  (const float*)d_in[5], (const float*)d_in[6],
                                  (const float*)d_in[7], B);
}